// round 9
// baseline (speedup 1.0000x reference)
#include <cuda_runtime.h>

// inputs: float32 [16, 64, 256, 256] NCHW
#define NB      16
#define NC      64
#define HW4     16384                 // float4 per (n,c) slice
#define SLICE4  (NC * HW4)
#define TPB     256
#define EPS     1e-5f

#define NR      16                    // rounds (channel groups of 4)
#define CPR     4                     // channels per round (16.75 MB live)
#define BPC     128                   // blocks per channel
#define NBLK    512                   // all co-resident (<= 148*4 slots)
#define ITERS   8                     // float4 per thread per tile (32 KB tile)

__device__ float g_sum[NC];
__device__ float g_sq [NC];
__device__ float g_scale[NC];         // rstd
__device__ float g_bias [NC];         // -mean*rstd
__device__ int   g_done [NC];         // per-channel reduce arrivals
__device__ int   g_ready[NC];         // per-channel stats published

__global__ void init_kernel() {
    const int t = threadIdx.x;
    if (t < NC) {
        g_sum[t] = 0.0f; g_sq[t] = 0.0f;
        g_done[t] = 0;   g_ready[t] = 0;
    }
}

// Reduce one 32 KB tile of channel c; fold into per-channel sums; the last
// arriving block of the channel finalizes scale/bias and raises ready[c].
__device__ __forceinline__ void reduce_tile(
    const float4* __restrict__ in, size_t base, int c,
    float* sh_s, float* sh_q, int tid, int lane, int wid)
{
    float s = 0.0f, q = 0.0f;
    {
        float4 v[ITERS];
        #pragma unroll
        for (int k = 0; k < ITERS; k++) v[k] = in[base + k * TPB];
        #pragma unroll
        for (int k = 0; k < ITERS; k++) {
            s += (v[k].x + v[k].y) + (v[k].z + v[k].w);
            q += (v[k].x * v[k].x + v[k].y * v[k].y)
               + (v[k].z * v[k].z + v[k].w * v[k].w);
        }
    }

    #pragma unroll
    for (int off = 16; off > 0; off >>= 1) {
        s += __shfl_down_sync(0xffffffffu, s, off);
        q += __shfl_down_sync(0xffffffffu, q, off);
    }
    if (lane == 0) { sh_s[wid] = s; sh_q[wid] = q; }
    __syncthreads();

    if (tid == 0) {
        float ss = sh_s[0], qq = sh_q[0];
        #pragma unroll
        for (int w = 1; w < 8; w++) { ss += sh_s[w]; qq += sh_q[w]; }
        atomicAdd(&g_sum[c], ss);
        atomicAdd(&g_sq [c], qq);
        __threadfence();
        const int old = atomicAdd(&g_done[c], 1);
        if (old == BPC - 1) {
            __threadfence();
            const float invN = 1.0f / (float)(NB * HW4 * 4);
            const float mean = g_sum[c] * invN;
            const float rstd = rsqrtf(g_sq[c] * invN - mean * mean + EPS);
            g_scale[c] = rstd;
            g_bias [c] = -mean * rstd;
            __threadfence();
            atomicExch(&g_ready[c], 1);
        }
    }
    __syncthreads();   // sh_s/sh_q safe for reuse
}

__global__ void __launch_bounds__(TPB, 4)
fused_kernel(const float4* __restrict__ in, float4* __restrict__ out) {
    const int tid  = threadIdx.x;
    const int lane = tid & 31;
    const int wid  = tid >> 5;

    // Block -> tile: 128 blocks per channel; tile = 1/8 of one (n,c) slice
    // (2048 float4 = 32 KB, contiguous).
    const int cidx = blockIdx.x >> 7;          // channel within round [0,4)
    const int b    = blockIdx.x & 127;         // block within channel
    const int n    = b >> 3;                   // batch index
    const int hw0  = (b & 7) * 2048;           // hw4 offset

    __shared__ float sh_s[8], sh_q[8];
    __shared__ float sh_sb[2];

    const size_t tbase = (size_t)n * SLICE4 + hw0 + tid;

    // ── pipeline fill: reduce round 0 ──
    reduce_tile(in, tbase + (size_t)cidx * HW4, cidx, sh_s, sh_q, tid, lane, wid);

    for (int g = 0; g < NR; g++) {
        const int c = g * CPR + cidx;

        // ── reduce next round first (hides the ready-wait below) ──
        if (g + 1 < NR) {
            const int cn = (g + 1) * CPR + cidx;
            reduce_tile(in, tbase + (size_t)cn * HW4, cn, sh_s, sh_q, tid, lane, wid);
        }

        // ── wait for my channel's stats (usually already set) ──
        if (tid == 0) {
            while (*((volatile int*)&g_ready[c]) == 0) __nanosleep(32);
            __threadfence();
            sh_sb[0] = g_scale[c];
            sh_sb[1] = g_bias [c];
        }
        __syncthreads();
        const float scale = sh_sb[0];
        const float bias  = sh_sb[1];

        // ── normalize my round-g tile (reads L2/L1-resident) ──
        const size_t base = tbase + (size_t)c * HW4;
        #pragma unroll
        for (int k = 0; k < ITERS; k++) {
            const size_t idx = base + k * TPB;
            float4 v = in[idx];
            float4 o;
            o.x = fmaf(v.x, scale, bias);
            o.y = fmaf(v.y, scale, bias);
            o.z = fmaf(v.z, scale, bias);
            o.w = fmaf(v.w, scale, bias);
            __stcs(&out[idx], o);
        }
        __syncthreads();   // sh_sb safe for next round
    }
}

extern "C" void kernel_launch(void* const* d_in, const int* in_sizes, int n_in,
                              void* d_out, int out_size) {
    const float4* in  = (const float4*)d_in[0];
    float4*       out = (float4*)d_out;

    init_kernel<<<1, 64>>>();
    fused_kernel<<<NBLK, TPB>>>(in, out);
}

// round 10
// speedup vs baseline: 1.0347x; 1.0347x over previous
#include <cuda_runtime.h>

// inputs: float32 [16, 64, 256, 256] NCHW
#define NB      16
#define NC      64
#define HW4     16384                 // float4 per (n,c) slice
#define SLICE4  (NC * HW4)
#define TPB     256
#define EPS     1e-5f

#define NR      16                    // rounds
#define CPR     4                     // channels per round
#define BPC     128                   // blocks per channel
#define NBLK    512                   // all co-resident (148 SMs * 4)
#define ITERS   8                     // float4 per thread per tile (32 KB tile)
#define TILE4   (ITERS * TPB)         // 2048 float4

__device__ float g_sum[NC];
__device__ float g_sq [NC];
__device__ float g_scale[NC];
__device__ float g_bias [NC];
__device__ int   g_done [NC];
__device__ int   g_ready[NC];

__global__ void init_kernel() {
    const int t = threadIdx.x;
    if (t < NC) {
        g_sum[t] = 0.0f; g_sq[t] = 0.0f;
        g_done[t] = 0;   g_ready[t] = 0;
    }
}

// Load tile into regs v[] and fold its sum/sumsq into channel c's accumulators.
// Last-arriving block of the channel finalizes scale/bias, raises ready[c].
__device__ __forceinline__ void load_reduce(
    const float4* __restrict__ in, size_t base, int c, float4* v,
    float* sh_s, float* sh_q, int tid, int lane, int wid)
{
    #pragma unroll
    for (int k = 0; k < ITERS; k++) v[k] = __ldcg(&in[base + k * TPB]);

    float s = 0.0f, q = 0.0f;
    #pragma unroll
    for (int k = 0; k < ITERS; k++) {
        s += (v[k].x + v[k].y) + (v[k].z + v[k].w);
        q += (v[k].x * v[k].x + v[k].y * v[k].y)
           + (v[k].z * v[k].z + v[k].w * v[k].w);
    }

    #pragma unroll
    for (int off = 16; off > 0; off >>= 1) {
        s += __shfl_down_sync(0xffffffffu, s, off);
        q += __shfl_down_sync(0xffffffffu, q, off);
    }
    if (lane == 0) { sh_s[wid] = s; sh_q[wid] = q; }
    __syncthreads();

    if (tid == 0) {
        float ss = sh_s[0], qq = sh_q[0];
        #pragma unroll
        for (int w = 1; w < 8; w++) { ss += sh_s[w]; qq += sh_q[w]; }
        atomicAdd(&g_sum[c], ss);
        atomicAdd(&g_sq [c], qq);
        __threadfence();
        const int old = atomicAdd(&g_done[c], 1);
        if (old == BPC - 1) {
            __threadfence();
            const float invN = 1.0f / (float)(NB * HW4 * 4);
            const float mean = g_sum[c] * invN;
            const float rstd = rsqrtf(g_sq[c] * invN - mean * mean + EPS);
            g_scale[c] = rstd;
            g_bias [c] = -mean * rstd;
            __threadfence();
            atomicExch(&g_ready[c], 1);
        }
    }
    __syncthreads();
}

__global__ void __launch_bounds__(TPB, 4)
fused_kernel(const float4* __restrict__ in, float4* __restrict__ out) {
    const int tid  = threadIdx.x;
    const int lane = tid & 31;
    const int wid  = tid >> 5;

    // 128 blocks per channel; tile = 1/8 of one (n,c) slice (2048 f4, 32 KB).
    const int cidx = blockIdx.x >> 7;
    const int b    = blockIdx.x & 127;
    const int n    = b >> 3;
    const int hw0  = (b & 7) * 2048;

    __shared__ float  sh_s[8], sh_q[8];
    __shared__ float  sh_sb[2];
    __shared__ float4 buf[TILE4];     // 32 KB stash; thread-private slots

    const size_t tbase = (size_t)n * SLICE4 + hw0 + tid;

    float4 v[ITERS];                  // 32 regs: current in-flight tile

    // ── fill: load+reduce round 0 into regs ──
    load_reduce(in, tbase + (size_t)cidx * HW4, cidx, v, sh_s, sh_q, tid, lane, wid);

    for (int g = 0; g < NR; g++) {
        const int c = g * CPR + cidx;

        // stash tile g (regs -> own smem slots; no sync needed, self-read-only)
        #pragma unroll
        for (int k = 0; k < ITERS; k++) buf[k * TPB + tid] = v[k];

        // issue round g+1's global loads + reduce (hides the ready-wait)
        if (g + 1 < NR) {
            const int cn = (g + 1) * CPR + cidx;
            load_reduce(in, tbase + (size_t)cn * HW4, cn, v, sh_s, sh_q, tid, lane, wid);
        }

        // wait for channel-g stats (usually already published)
        if (tid == 0) {
            while (*((volatile int*)&g_ready[c]) == 0) __nanosleep(32);
            __threadfence();
            sh_sb[0] = g_scale[c];
            sh_sb[1] = g_bias [c];
        }
        __syncthreads();
        const float scale = sh_sb[0];
        const float bias  = sh_sb[1];

        // normalize tile g from the smem stash: zero global re-reads
        const size_t base = tbase + (size_t)c * HW4;
        #pragma unroll
        for (int k = 0; k < ITERS; k++) {
            float4 t = buf[k * TPB + tid];
            float4 o;
            o.x = fmaf(t.x, scale, bias);
            o.y = fmaf(t.y, scale, bias);
            o.z = fmaf(t.z, scale, bias);
            o.w = fmaf(t.w, scale, bias);
            __stcs(&out[base + k * TPB], o);
        }
    }
}

extern "C" void kernel_launch(void* const* d_in, const int* in_sizes, int n_in,
                              void* d_out, int out_size) {
    const float4* in  = (const float4*)d_in[0];
    float4*       out = (float4*)d_out;

    init_kernel<<<1, 64>>>();
    fused_kernel<<<NBLK, TPB>>>(in, out);
}